// round 8
// baseline (speedup 1.0000x reference)
#include <cuda_runtime.h>
#include <cstdint>

// SoftReordering, R7: T=2 t-blocking + warp-per-t split in step 1.
//   CTA owns (t0, t1). 8 warps = 2 t-groups x 4 warps x 4 batches.
//   Each warp reads only its t's 7 weight rows from smem -> weight LDS
//   redundancy drops 8 -> 4 (L1 crossbar was the co-binder at R6).
//   Step 2 re-partitions (warp = 2 batches, both t's, 8 shared x rows);
//   gates exchanged via 1KB smem. 3-buffer cp.async ring, ONE barrier/phase.

#define SSEQ 1024
#define EE   1024
#define WW   7
#define WE   7168                  // W*E
#define HALF 512                   // e-half chunk (floats)
#define SLABF (14 * HALF)          // floats per slab = 7168 (28KB)
#define NBUF 3
#define GATE_OFF (NBUF * SLABF)
#define SMEM_BYTES ((NBUF * SLABF + 16 * 16) * 4)   // 87040

__device__ __forceinline__ uint32_t smem_u32(const void* p) {
    uint32_t a;
    asm("{ .reg .u64 t; cvta.to.shared.u64 t, %1; cvt.u32.u64 %0, t; }"
        : "=r"(a) : "l"(p));
    return a;
}
__device__ __forceinline__ void cp_async16(uint32_t saddr, const void* gptr) {
    asm volatile("cp.async.cg.shared.global [%0], [%1], 16;"
                 :: "r"(saddr), "l"(gptr));
}
__device__ __forceinline__ void cp_commit() {
    asm volatile("cp.async.commit_group;");
}
template <int N>
__device__ __forceinline__ void cp_wait() {
    asm volatile("cp.async.wait_group %0;" :: "n"(N));
}
__device__ __forceinline__ void ffma2(unsigned long long& d,
                                      unsigned long long a,
                                      unsigned long long b) {
    asm("fma.rn.f32x2 %0, %1, %2, %3;" : "=l"(d) : "l"(a), "l"(b), "l"(d));
}
__device__ __forceinline__ float2 unpack2(unsigned long long v) {
    float2 r;
    asm("mov.b64 {%0, %1}, %2;" : "=f"(r.x), "=f"(r.y) : "l"(v));
    return r;
}
__device__ __forceinline__ float tanh_ap(float x) {
    float r;
    asm("tanh.approx.f32 %0, %1;" : "=f"(r) : "f"(x));
    return r;
}

__global__ void __launch_bounds__(256, 2)
soft_reorder_kernel(const float* __restrict__ x,
                    const float* __restrict__ wgt,
                    const float* __restrict__ bias,
                    float* __restrict__ out) {
    extern __shared__ float smem[];
    float* s_gates = smem + GATE_OFF;      // [batch][tt*8 + v], 16x16 floats

    const int t0   = (int)blockIdx.x * 2;
    const int t1   = t0 + 1;
    const int tid  = threadIdx.x;
    const int lane = tid & 31;
    const int warp = tid >> 5;
    const int tsel = warp >> 2;            // which t this warp computes logits for
    const int b0   = (warp & 3) << 2;      // warp's 4 batches (step 1)
    const int tw   = t0 + tsel;
    const uint32_t sbase = smem_u32(smem);

    // Slab for phase p = i*2+h: rows 0-6 = weight[t0, v, i*E + h*HALF ..],
    //                           rows 7-13 = weight[t1, v, (i-1)*E + h*HALF ..].
    auto stage = [&](int p, int buf) {
        const int i = p >> 1, h = p & 1;
        const int r = t0 - 3 + i;
        if (r >= 0 && r < SSEQ) {
            const uint32_t dst = sbase + (uint32_t)buf * (SLABF * 4);
#pragma unroll
            for (int k = 0; k < 7; ++k) {
                const int j   = tid + (k << 8);     // 0..1791
                const int row = j >> 7;             // 0..13
                const int col = (j & 127) << 2;     // float offset in half-row
                const float* src;
                bool ok;
                if (row < 7) {
                    ok  = (i < 7);
                    src = wgt + (size_t)(t0 * WW + row) * WE
                              + (size_t)i * EE + h * HALF + col;
                } else {
                    ok  = (i >= 1);
                    src = wgt + (size_t)(t1 * WW + (row - 7)) * WE
                              + (size_t)(i - 1) * EE + h * HALF + col;
                }
                if (ok)
                    cp_async16(dst + (uint32_t)(row * HALF + col) * 4, src);
            }
        }
        cp_commit();
    };

    // ------------------------------------------------------------------
    // Step 1: logits for this warp's t, 4 batches.  acc[v][bb] (f32x2).
    // ------------------------------------------------------------------
    unsigned long long acc[7][4];
#pragma unroll
    for (int v = 0; v < 7; ++v)
#pragma unroll
        for (int bb = 0; bb < 4; ++bb)
            acc[v][bb] = 0ull;

    stage(0, 0);
    stage(1, 1);
    for (int p = 0; p < 16; ++p) {
        cp_wait<1>();          // group p complete (group p+1 still pending)
        __syncthreads();       // all warps done with phase p-1; slab p visible
        if (p + 2 < 16) stage(p + 2, (p + 2) % 3);   // overwrites buf of p-1

        const int i = p >> 1, h = p & 1;
        const int r = t0 - 3 + i;
        const bool tap_ok = tsel ? (i >= 1) : (i < 7);
        if (r >= 0 && r < SSEQ && tap_ok) {
            const float* xr = x + ((size_t)b0 * SSEQ + r) * EE + h * HALF;
            const float* wb = smem + (p % 3) * SLABF + tsel * 7 * HALF;
#pragma unroll
            for (int c = 0; c < 4; ++c) {
                const int el = (c << 7) + (lane << 2);
                ulonglong2 xv[4];
#pragma unroll
                for (int bb = 0; bb < 4; ++bb)
                    xv[bb] = *reinterpret_cast<const ulonglong2*>(
                        xr + (size_t)bb * SSEQ * EE + el);
#pragma unroll
                for (int v = 0; v < 7; ++v) {
                    const ulonglong2 wv = *reinterpret_cast<const ulonglong2*>(
                        wb + v * HALF + el);                    // LDS.128
#pragma unroll
                    for (int bb = 0; bb < 4; ++bb) {
                        ffma2(acc[v][bb], xv[bb].x, wv.x);
                        ffma2(acc[v][bb], xv[bb].y, wv.y);
                    }
                }
            }
        }
    }

    // Reduce over lanes, apply sigmoid, publish gates to smem.
#pragma unroll
    for (int v = 0; v < 7; ++v) {
        const float bz = bias[tw * WW + v];
#pragma unroll
        for (int bb = 0; bb < 4; ++bb) {
            const float2 q = unpack2(acc[v][bb]);
            float s = q.x + q.y;
#pragma unroll
            for (int o = 16; o > 0; o >>= 1)
                s += __shfl_xor_sync(0xffffffffu, s, o);
            if (lane == 0) {
                const float z = s + bz;
                s_gates[(b0 + bb) * 16 + tsel * 8 + v] =
                    1.0f / (1.0f + __expf(-z));
            }
        }
    }
    __syncthreads();

    // ------------------------------------------------------------------
    // Step 2: warp owns batches (2*warp, 2*warp+1), BOTH t's, 8 shared rows.
    // ------------------------------------------------------------------
    const int sb0 = warp << 1;
    float g[2][7][2];          // [tt][tap][bb]
#pragma unroll
    for (int tt = 0; tt < 2; ++tt)
#pragma unroll
        for (int v = 0; v < 7; ++v)
#pragma unroll
            for (int bb = 0; bb < 2; ++bb)
                g[tt][v][bb] = s_gates[(sb0 + bb) * 16 + tt * 8 + v];

#pragma unroll
    for (int c = 0; c < 8; ++c) {
        const int e = (c << 7) + (lane << 2);
        const float* xe = x + (size_t)sb0 * SSEQ * EE + e;
        float4 o[2][2];
#pragma unroll
        for (int tt = 0; tt < 2; ++tt)
#pragma unroll
            for (int bb = 0; bb < 2; ++bb)
                o[tt][bb] = make_float4(0.f, 0.f, 0.f, 0.f);

#pragma unroll
        for (int i = 0; i < 8; ++i) {
            const int r = t0 - 3 + i;
            if (r >= 0 && r < SSEQ) {
                const float4 xA = *reinterpret_cast<const float4*>(
                    xe + (size_t)r * EE);
                const float4 xB = *reinterpret_cast<const float4*>(
                    xe + (size_t)(SSEQ + r) * EE);
                if (i < 7) {              // tap i for t0
                    const float gA = g[0][i][0], gB = g[0][i][1];
                    o[0][0].x += gA * xA.x; o[0][0].y += gA * xA.y;
                    o[0][0].z += gA * xA.z; o[0][0].w += gA * xA.w;
                    o[0][1].x += gB * xB.x; o[0][1].y += gB * xB.y;
                    o[0][1].z += gB * xB.z; o[0][1].w += gB * xB.w;
                }
                if (i >= 1) {             // tap i-1 for t1
                    const float gA = g[1][i - 1][0], gB = g[1][i - 1][1];
                    o[1][0].x += gA * xA.x; o[1][0].y += gA * xA.y;
                    o[1][0].z += gA * xA.z; o[1][0].w += gA * xA.w;
                    o[1][1].x += gB * xB.x; o[1][1].y += gB * xB.y;
                    o[1][1].z += gB * xB.z; o[1][1].w += gB * xB.w;
                }
            }
        }
#pragma unroll
        for (int tt = 0; tt < 2; ++tt)
#pragma unroll
            for (int bb = 0; bb < 2; ++bb) {
                float4 ov;
                ov.x = tanh_ap(o[tt][bb].x);
                ov.y = tanh_ap(o[tt][bb].y);
                ov.z = tanh_ap(o[tt][bb].z);
                ov.w = tanh_ap(o[tt][bb].w);
                *reinterpret_cast<float4*>(
                    out + ((size_t)(sb0 + bb) * SSEQ + (tt ? t1 : t0)) * EE + e)
                    = ov;
            }
    }
}

extern "C" void kernel_launch(void* const* d_in, const int* in_sizes, int n_in,
                              void* d_out, int out_size) {
    const float* x    = (const float*)d_in[0];
    const float* wgt  = (const float*)d_in[1];
    const float* bias = (const float*)d_in[2];
    float* out        = (float*)d_out;

    static bool attr_set = false;
    if (!attr_set) {
        cudaFuncSetAttribute(soft_reorder_kernel,
                             cudaFuncAttributeMaxDynamicSharedMemorySize,
                             SMEM_BYTES);
        attr_set = true;
    }
    soft_reorder_kernel<<<SSEQ / 2, 256, SMEM_BYTES>>>(x, wgt, bias, out);
}

// round 11
// speedup vs baseline: 1.3666x; 1.3666x over previous
#include <cuda_runtime.h>
#include <cstdint>

// SoftReordering, R8: T=2 t-blocking, warps split by e-chunk (not by t).
//   8 warps = 2 e-chunks x 4 batch-groups. Each warp: 4 batches (packed in
//   pairs into f32x2 accumulators), BOTH t's, 256-float e-slice per phase.
//   x redundancy 1 (R7's bug was 2), weight LDS redundancy 4 (R6 was 8).
//   3-buffer cp.async ring, one barrier/phase, final-phase wait bug fixed.
//   Cross-e-chunk logit reduction via smem partials; step 2 in R6 shape.

#define SSEQ 1024
#define EE   1024
#define WW   7
#define WE   7168
#define HALF 512                     // floats per phase (e-half)
#define SLABF (14 * HALF)            // 28KB slab: 14 (t,v) rows x 512
#define NBUF 3
#define PART_OFF (NBUF * SLABF)      // float offset of partials
#define PART_FLOATS (2 * 4 * 2 * 7 * 2 * 2)   // ec,bg,tt,v,pair,half = 448
#define SMEM_BYTES ((NBUF * SLABF + PART_FLOATS) * 4)   // 87808

__device__ __forceinline__ uint32_t smem_u32(const void* p) {
    uint32_t a;
    asm("{ .reg .u64 t; cvta.to.shared.u64 t, %1; cvt.u32.u64 %0, t; }"
        : "=r"(a) : "l"(p));
    return a;
}
__device__ __forceinline__ void cp_async16(uint32_t saddr, const void* gptr) {
    asm volatile("cp.async.cg.shared.global [%0], [%1], 16;"
                 :: "r"(saddr), "l"(gptr));
}
__device__ __forceinline__ void cp_commit() {
    asm volatile("cp.async.commit_group;");
}
template <int N>
__device__ __forceinline__ void cp_wait() {
    asm volatile("cp.async.wait_group %0;" :: "n"(N));
}
__device__ __forceinline__ void ffma2(unsigned long long& d,
                                      unsigned long long a,
                                      unsigned long long b) {
    asm("fma.rn.f32x2 %0, %1, %2, %3;" : "=l"(d) : "l"(a), "l"(b), "l"(d));
}
__device__ __forceinline__ unsigned long long pack2(float lo, float hi) {
    unsigned long long p;
    asm("mov.b64 %0, {%1, %2};" : "=l"(p) : "f"(lo), "f"(hi));
    return p;
}
__device__ __forceinline__ unsigned long long pack_dup(float g) {
    unsigned long long p;
    asm("mov.b64 %0, {%1, %1};" : "=l"(p) : "f"(g));
    return p;
}
__device__ __forceinline__ float2 unpack2(unsigned long long v) {
    float2 r;
    asm("mov.b64 {%0, %1}, %2;" : "=f"(r.x), "=f"(r.y) : "l"(v));
    return r;
}
__device__ __forceinline__ unsigned long long add2(unsigned long long a,
                                                   unsigned long long b) {
    unsigned long long d;
    asm("add.rn.f32x2 %0, %1, %2;" : "=l"(d) : "l"(a), "l"(b));
    return d;
}
__device__ __forceinline__ unsigned long long shfl_xor_u64(unsigned long long v,
                                                           int m) {
    uint32_t lo = (uint32_t)v, hi = (uint32_t)(v >> 32);
    lo = __shfl_xor_sync(0xffffffffu, lo, m);
    hi = __shfl_xor_sync(0xffffffffu, hi, m);
    return ((unsigned long long)hi << 32) | lo;
}
__device__ __forceinline__ float tanh_ap(float x) {
    float r;
    asm("tanh.approx.f32 %0, %1;" : "=f"(r) : "f"(x));
    return r;
}

__global__ void __launch_bounds__(256, 2)
soft_reorder_kernel(const float* __restrict__ x,
                    const float* __restrict__ wgt,
                    const float* __restrict__ bias,
                    float* __restrict__ out) {
    extern __shared__ float smem[];
    unsigned long long* s_part =
        reinterpret_cast<unsigned long long*>(smem + PART_OFF);
    const float* s_partf = smem + PART_OFF;

    const int t0   = (int)blockIdx.x * 2;
    const int t1   = t0 + 1;
    const int tid  = threadIdx.x;
    const int lane = tid & 31;
    const int warp = tid >> 5;
    const int ec   = warp & 1;            // e-chunk (0: [0,256), 1: [256,512))
    const int bg   = warp >> 2 ? (warp >> 1) & 3 : (warp >> 1); // = warp>>1
    const int b0   = (warp >> 1) << 2;    // batch group base (4 batches)
    const uint32_t sbase = smem_u32(smem);

    // Slab phase p = i*2+h: rows 0-6 = weight[t0, v, i*E + h*HALF ..],
    //                       rows 7-13 = weight[t1, v, (i-1)*E + h*HALF ..].
    auto stage = [&](int p, int buf) {
        const int i = p >> 1, h = p & 1;
        const int r = t0 - 3 + i;
        if (r >= 0 && r < SSEQ) {
            const uint32_t dst = sbase + (uint32_t)buf * (SLABF * 4);
#pragma unroll
            for (int k = 0; k < 7; ++k) {
                const int j   = tid + (k << 8);     // 0..1791
                const int row = j >> 7;             // 0..13
                const int col = (j & 127) << 2;
                const float* src;
                bool ok;
                if (row < 7) {
                    ok  = (i < 7);
                    src = wgt + (size_t)(t0 * WW + row) * WE
                              + (size_t)i * EE + h * HALF + col;
                } else {
                    ok  = (i >= 1);
                    src = wgt + (size_t)(t1 * WW + (row - 7)) * WE
                              + (size_t)(i - 1) * EE + h * HALF + col;
                }
                if (ok)
                    cp_async16(dst + (uint32_t)(row * HALF + col) * 4, src);
            }
        }
        cp_commit();
    };

    // ------------------------------------------------------------------
    // Step 1: acc[tt][v][pair] packed over batch pairs (b0+2p, b0+2p+1).
    // ------------------------------------------------------------------
    unsigned long long acc[2][7][2];
#pragma unroll
    for (int tt = 0; tt < 2; ++tt)
#pragma unroll
        for (int v = 0; v < 7; ++v)
#pragma unroll
            for (int pr = 0; pr < 2; ++pr)
                acc[tt][v][pr] = 0ull;

    stage(0, 0);
    stage(1, 1);
    for (int p = 0; p < 16; ++p) {
        const int i = p >> 1, h = p & 1;
        const int r = t0 - 3 + i;
        const bool rv = (r >= 0 && r < SSEQ);

        // Front-issue x loads: overlap LDG latency with cp_wait + barrier.
        float4 xv[2][4];
        if (rv) {
            const float* xr = x + ((size_t)b0 * SSEQ + r) * EE
                                + h * HALF + ec * 256 + (lane << 2);
#pragma unroll
            for (int c = 0; c < 2; ++c)
#pragma unroll
                for (int bb = 0; bb < 4; ++bb)
                    xv[c][bb] = *reinterpret_cast<const float4*>(
                        xr + (size_t)bb * SSEQ * EE + (c << 7));
        }

        if (p < 15) cp_wait<1>(); else cp_wait<0>();
        __syncthreads();                    // slab p visible; p-1 consumers done
        if (p + 2 < 16) stage(p + 2, (p + 2) % 3);

        if (rv) {
            const float* wb = smem + (p % 3) * SLABF + ec * 256 + (lane << 2);
            const bool tap0 = (i < 7), tap1 = (i >= 1);
#pragma unroll
            for (int c = 0; c < 2; ++c) {
                unsigned long long pk[2][4];
#pragma unroll
                for (int k = 0; k < 4; ++k) {
                    const float* a0 = &xv[c][0].x;
                    const float* a1 = &xv[c][1].x;
                    const float* a2 = &xv[c][2].x;
                    const float* a3 = &xv[c][3].x;
                    pk[0][k] = pack2(a0[k], a1[k]);
                    pk[1][k] = pack2(a2[k], a3[k]);
                }
                if (tap0) {
#pragma unroll
                    for (int v = 0; v < 7; ++v) {
                        const float4 wv = *reinterpret_cast<const float4*>(
                            wb + v * HALF + (c << 7));          // LDS.128
                        const float* wk = &wv.x;
#pragma unroll
                        for (int k = 0; k < 4; ++k) {
                            const unsigned long long dw = pack_dup(wk[k]);
                            ffma2(acc[0][v][0], dw, pk[0][k]);
                            ffma2(acc[0][v][1], dw, pk[1][k]);
                        }
                    }
                }
                if (tap1) {
#pragma unroll
                    for (int v = 0; v < 7; ++v) {
                        const float4 wv = *reinterpret_cast<const float4*>(
                            wb + (7 + v) * HALF + (c << 7));
                        const float* wk = &wv.x;
#pragma unroll
                        for (int k = 0; k < 4; ++k) {
                            const unsigned long long dw = pack_dup(wk[k]);
                            ffma2(acc[1][v][0], dw, pk[0][k]);
                            ffma2(acc[1][v][1], dw, pk[1][k]);
                        }
                    }
                }
            }
        }
    }

    // Lane reduction (packed halves stay separate: lo = batch 2p, hi = 2p+1),
    // then publish per-(ec,bg) partials to smem.
#pragma unroll
    for (int tt = 0; tt < 2; ++tt)
#pragma unroll
        for (int v = 0; v < 7; ++v)
#pragma unroll
            for (int pr = 0; pr < 2; ++pr) {
                unsigned long long s = acc[tt][v][pr];
#pragma unroll
                for (int o = 16; o > 0; o >>= 1)
                    s = add2(s, shfl_xor_u64(s, o));
                if (lane == 0)
                    s_part[(((ec << 2) | (warp >> 1)) * 14 + tt * 7 + v) * 2 + pr] = s;
            }
    __syncthreads();

    // ------------------------------------------------------------------
    // Step 2: warp owns batches (2*warp, 2*warp+1), both t's, 8 rows, full e.
    // ------------------------------------------------------------------
    const int sb0 = warp << 1;
    unsigned long long gg[2][7][2];       // [tt][tap][bb] gate, duplicated
#pragma unroll
    for (int bb = 0; bb < 2; ++bb) {
        const int sb  = sb0 + bb;
        const int bg2 = sb >> 2;
        const int pr  = (sb >> 1) & 1;
        const int hf  = sb & 1;
#pragma unroll
        for (int tt = 0; tt < 2; ++tt)
#pragma unroll
            for (int v = 0; v < 7; ++v) {
                const int base = ((bg2 * 14 + tt * 7 + v) * 2 + pr) * 2 + hf;
                const float z = s_partf[base]
                              + s_partf[(4 * 14 * 2) * 2 + base]   // ec=1 block
                              + bias[(t0 + tt) * WW + v];
                gg[tt][v][bb] = pack_dup(1.0f / (1.0f + __expf(-z)));
            }
    }

#pragma unroll
    for (int c = 0; c < 8; ++c) {
        const int e = (c << 7) + (lane << 2);
        const float* xe = x + (size_t)sb0 * SSEQ * EE + e;
        unsigned long long o[2][2][2];
#pragma unroll
        for (int tt = 0; tt < 2; ++tt)
#pragma unroll
            for (int bb = 0; bb < 2; ++bb) {
                o[tt][bb][0] = 0ull; o[tt][bb][1] = 0ull;
            }
#pragma unroll
        for (int i = 0; i < 8; ++i) {
            const int r = t0 - 3 + i;
            if (r >= 0 && r < SSEQ) {
                const ulonglong2 xA = *reinterpret_cast<const ulonglong2*>(
                    xe + (size_t)r * EE);
                const ulonglong2 xB = *reinterpret_cast<const ulonglong2*>(
                    xe + (size_t)(SSEQ + r) * EE);
                if (i < 7) {
                    ffma2(o[0][0][0], gg[0][i][0], xA.x);
                    ffma2(o[0][0][1], gg[0][i][0], xA.y);
                    ffma2(o[0][1][0], gg[0][i][1], xB.x);
                    ffma2(o[0][1][1], gg[0][i][1], xB.y);
                }
                if (i >= 1) {
                    ffma2(o[1][0][0], gg[1][i - 1][0], xA.x);
                    ffma2(o[1][0][1], gg[1][i - 1][0], xA.y);
                    ffma2(o[1][1][0], gg[1][i - 1][1], xB.x);
                    ffma2(o[1][1][1], gg[1][i - 1][1], xB.y);
                }
            }
        }
#pragma unroll
        for (int tt = 0; tt < 2; ++tt)
#pragma unroll
            for (int bb = 0; bb < 2; ++bb) {
                const float2 p0 = unpack2(o[tt][bb][0]);
                const float2 p1 = unpack2(o[tt][bb][1]);
                float4 ov;
                ov.x = tanh_ap(p0.x);
                ov.y = tanh_ap(p0.y);
                ov.z = tanh_ap(p1.x);
                ov.w = tanh_ap(p1.y);
                *reinterpret_cast<float4*>(
                    out + ((size_t)(sb0 + bb) * SSEQ + (tt ? t1 : t0)) * EE + e)
                    = ov;
            }
    }
}

extern "C" void kernel_launch(void* const* d_in, const int* in_sizes, int n_in,
                              void* d_out, int out_size) {
    const float* x    = (const float*)d_in[0];
    const float* wgt  = (const float*)d_in[1];
    const float* bias = (const float*)d_in[2];
    float* out        = (float*)d_out;

    static bool attr_set = false;
    if (!attr_set) {
        cudaFuncSetAttribute(soft_reorder_kernel,
                             cudaFuncAttributeMaxDynamicSharedMemorySize,
                             SMEM_BYTES);
        attr_set = true;
    }
    soft_reorder_kernel<<<SSEQ / 2, 256, SMEM_BYTES>>>(x, wgt, bias, out);
}